// round 11
// baseline (speedup 1.0000x reference)
#include <cuda_runtime.h>
#include <math.h>

typedef unsigned long long ull;

#define FMA2(d, a, b) asm("fma.rn.f32x2 %0, %1, %2, %0;" : "+l"(d) : "l"(a), "l"(b))
#define MUL2(d, a, b) asm("mul.rn.f32x2 %0, %1, %2;" : "=l"(d) : "l"(a), "l"(b))

__device__ __forceinline__ ull dup2f(float a) {
    ull r; asm("mov.b64 %0, {%1, %1};" : "=l"(r) : "f"(a)); return r;
}
__device__ __forceinline__ float2 unpk(ull v) {
    float2 f; asm("mov.b64 {%0, %1}, %2;" : "=f"(f.x), "=f"(f.y) : "l"(v)); return f;
}
// 128-bit L2 load: two packed f32x2 operands in one LDG.128
__device__ __forceinline__ void ldcg_v2u64(const float* p, ull& lo, ull& hi) {
    asm volatile("ld.global.cg.v2.u64 {%0, %1}, [%2];" : "=l"(lo), "=l"(hi) : "l"(p));
}
__device__ __forceinline__ unsigned acq_load(const unsigned* p) {
    unsigned v;
    asm volatile("ld.acquire.gpu.global.u32 %0, [%1];" : "=r"(v) : "l"(p) : "memory");
    return v;
}

// ---------------- device scratch ----------------
// gate pre [dir*128+slice][t][8][32] : sub 0..3 = r cols (slice*4+j), 4..7 = u cols
__device__ float g_preG[(size_t)2 * 128 * 512 * 8 * 32];
// cand pre [dir*128+slice][t][4][32]
__device__ float g_preC[(size_t)2 * 128 * 512 * 4 * 32];
__device__ float g_xt [(size_t)512 * 32 * 256];  // x: [t][b][c]
__device__ float g_outf[(size_t)512 * 32 * 512]; // fw hidden [t][b][h]
__device__ float g_outb[(size_t)512 * 32 * 512]; // bw hidden [t][b][h]
// h quad-interleaved, PARITY double-buffered: [dir][par][kquad 128][b 32][4]
__device__ float g_hQ [2 * 2 * 128 * 32 * 4];
// r quad-interleaved, parity double-buffered, same layout
__device__ float g_rQ [2 * 2 * 128 * 32 * 4];
__device__ float g_pool[32 * 512];
// distributed flags: one padded word per slice (128B apart), per direction/phase
__device__ unsigned g_flagA[2][128 * 32];
__device__ unsigned g_flagB[2][128 * 32];

// ---------------- init ----------------
__global__ void k_init() {
    int i = blockIdx.x * blockDim.x + threadIdx.x;   // 65536 threads
    if (i < 2 * 2 * 128 * 32 * 4) { g_hQ[i] = 0.f; g_rQ[i] = 0.f; }
    if (i < 32 * 512) g_pool[i] = 0.f;
    if (i < 2 * 128 * 32) { ((unsigned*)g_flagA)[i] = 0u; ((unsigned*)g_flagB)[i] = 0u; }
}

// ---------------- x -> [t][b][c] copy ----------------
__global__ void k_xcopy(const float* __restrict__ x) {
    int idx = blockIdx.x * blockDim.x + threadIdx.x;  // float4 id
    if (idx < 32 * 512 * 64) {
        int row = idx >> 6, c4 = idx & 63;            // row = b*512 + t
        int b = row >> 9, t = row & 511;
        ((float4*)g_xt)[(size_t)(t * 32 + b) * 64 + c4] = ((const float4*)x)[idx];
    }
}

// ---------------- GEMM1: x-part projections (M=16384,K=256,N=3072), double-buffered ----------------
__global__ __launch_bounds__(256, 2) void k_gemm_pre(
    const float* __restrict__ x,
    const float* __restrict__ fwWg, const float* __restrict__ fwbg,
    const float* __restrict__ fwWc, const float* __restrict__ fwbc,
    const float* __restrict__ bwWg, const float* __restrict__ bwbg,
    const float* __restrict__ bwWc, const float* __restrict__ bwbc)
{
    __shared__ __align__(16) float As[2][16 * 132];
    __shared__ __align__(16) float Bs[2][16 * 132];
    const int n0 = blockIdx.x * 128;
    const int m0 = blockIdx.y * 128;
    const float* W; const float* bias; int ld, nrel, dir, isC;
    if (n0 < 1024)      { W = fwWg; bias = fwbg; ld = 1024; nrel = n0;        dir = 0; isC = 0; }
    else if (n0 < 1536) { W = fwWc; bias = fwbc; ld = 512;  nrel = n0 - 1024; dir = 0; isC = 1; }
    else if (n0 < 2560) { W = bwWg; bias = bwbg; ld = 1024; nrel = n0 - 1536; dir = 1; isC = 0; }
    else                { W = bwWc; bias = bwbc; ld = 512;  nrel = n0 - 2560; dir = 1; isC = 1; }
    const int tid = threadIdx.x;
    const int tx = tid & 15, ty = tid >> 4;
    const int ar0 = tid >> 2, ac0 = (tid & 3) * 4;
    const int ar1 = (tid + 256) >> 2;
    const int bk0 = tid >> 5, bn0 = (tid & 31) * 4;
    const int bk1 = (tid + 256) >> 5;

    ull acc[8][4];
#pragma unroll
    for (int i = 0; i < 8; i++)
#pragma unroll
        for (int j = 0; j < 4; j++) acc[i][j] = 0ull;

    float4 pa0, pa1, pb0, pb1;
    pa0 = *(const float4*)&x[(size_t)(m0 + ar0) * 256 + ac0];
    pa1 = *(const float4*)&x[(size_t)(m0 + ar1) * 256 + ac0];
    pb0 = *(const float4*)&W[(size_t)bk0 * ld + nrel + bn0];
    pb1 = *(const float4*)&W[(size_t)bk1 * ld + nrel + bn0];
    {
        As[0][(ac0 + 0) * 132 + ar0] = pa0.x; As[0][(ac0 + 1) * 132 + ar0] = pa0.y;
        As[0][(ac0 + 2) * 132 + ar0] = pa0.z; As[0][(ac0 + 3) * 132 + ar0] = pa0.w;
        As[0][(ac0 + 0) * 132 + ar1] = pa1.x; As[0][(ac0 + 1) * 132 + ar1] = pa1.y;
        As[0][(ac0 + 2) * 132 + ar1] = pa1.z; As[0][(ac0 + 3) * 132 + ar1] = pa1.w;
        *(float4*)&Bs[0][bk0 * 132 + bn0] = pb0;
        *(float4*)&Bs[0][bk1 * 132 + bn0] = pb1;
    }
    __syncthreads();
    int p = 0;
    for (int slab = 0; slab < 16; ++slab) {
        if (slab < 15) {
            int k0 = (slab + 1) * 16;
            pa0 = *(const float4*)&x[(size_t)(m0 + ar0) * 256 + k0 + ac0];
            pa1 = *(const float4*)&x[(size_t)(m0 + ar1) * 256 + k0 + ac0];
            pb0 = *(const float4*)&W[(size_t)(k0 + bk0) * ld + nrel + bn0];
            pb1 = *(const float4*)&W[(size_t)(k0 + bk1) * ld + nrel + bn0];
        }
#pragma unroll
        for (int kk = 0; kk < 16; ++kk) {
            float4 a0 = *(const float4*)&As[p][kk * 132 + ty * 8];
            float4 a1 = *(const float4*)&As[p][kk * 132 + ty * 8 + 4];
            ulonglong2 w01 = *(const ulonglong2*)&Bs[p][kk * 132 + tx * 8];
            ulonglong2 w23 = *(const ulonglong2*)&Bs[p][kk * 132 + tx * 8 + 4];
            ull ad[8];
            ad[0] = dup2f(a0.x); ad[1] = dup2f(a0.y); ad[2] = dup2f(a0.z); ad[3] = dup2f(a0.w);
            ad[4] = dup2f(a1.x); ad[5] = dup2f(a1.y); ad[6] = dup2f(a1.z); ad[7] = dup2f(a1.w);
#pragma unroll
            for (int i = 0; i < 8; i++) {
                FMA2(acc[i][0], ad[i], w01.x);
                FMA2(acc[i][1], ad[i], w01.y);
                FMA2(acc[i][2], ad[i], w23.x);
                FMA2(acc[i][3], ad[i], w23.y);
            }
        }
        if (slab < 15) {
            int q = p ^ 1;
            As[q][(ac0 + 0) * 132 + ar0] = pa0.x; As[q][(ac0 + 1) * 132 + ar0] = pa0.y;
            As[q][(ac0 + 2) * 132 + ar0] = pa0.z; As[q][(ac0 + 3) * 132 + ar0] = pa0.w;
            As[q][(ac0 + 0) * 132 + ar1] = pa1.x; As[q][(ac0 + 1) * 132 + ar1] = pa1.y;
            As[q][(ac0 + 2) * 132 + ar1] = pa1.z; As[q][(ac0 + 3) * 132 + ar1] = pa1.w;
            *(float4*)&Bs[q][bk0 * 132 + bn0] = pb0;
            *(float4*)&Bs[q][bk1 * 132 + bn0] = pb1;
            __syncthreads();
            p = q;
        }
    }
    float4 bb0 = *(const float4*)&bias[nrel + tx * 8];
    float4 bb1 = *(const float4*)&bias[nrel + tx * 8 + 4];
    float bcol[8] = {bb0.x, bb0.y, bb0.z, bb0.w, bb1.x, bb1.y, bb1.z, bb1.w};
    const int cbase = nrel + tx * 8;
#pragma unroll
    for (int i = 0; i < 8; i++) {
        int m = m0 + ty * 8 + i;
        int t = m & 511, bb = m >> 9;
        float vals[8];
#pragma unroll
        for (int j = 0; j < 4; j++) {
            float2 v = unpk(acc[i][j]);
            vals[2 * j] = v.x + bcol[2 * j];
            vals[2 * j + 1] = v.y + bcol[2 * j + 1];
        }
#pragma unroll
        for (int cc = 0; cc < 8; ++cc) {
            int n = cbase + cc;
            if (!isC) {
                int c, sub;
                if (n < 512) { c = n >> 2; sub = n & 3; }
                else         { c = (n - 512) >> 2; sub = 4 + (n & 3); }
                g_preG[(((size_t)(dir * 128 + c) * 512 + t) * 8 + sub) * 32 + bb] = vals[cc];
            } else {
                int c = n >> 2, sub = n & 3;
                g_preC[(((size_t)(dir * 128 + c) * 512 + t) * 4 + sub) * 32 + bb] = vals[cc];
            }
        }
    }
}

// ---------------- flag publish (CTA-wide) + per-warp consumer wait ----------------
__device__ __forceinline__ void arrive_flag(unsigned* flag, int slice, unsigned val) {
    __syncthreads();
    if (threadIdx.x == 0) {
        __threadfence();
        *(volatile unsigned*)&flag[slice * 32] = val;
    }
}
// warp waits only on its 16 producer slices (cols 64w..64w+64 -> slices 16w..16w+16)
__device__ __forceinline__ void warp_wait(const unsigned* flag, int prod0, unsigned target) {
    int lane = threadIdx.x & 31;
    if (lane < 16) {
        const unsigned* fp = &flag[(prod0 + lane) * 32];
        while (acq_load(fp) < target) { }
    }
    __syncwarp();
}

// ---------------- persistent bidirectional GRU ----------------
// 256 CTAs x 256 threads, 2 CTAs/SM (fw+bw interleave at SMSP level).
// dir = cta&1, slice = cta>>1 (128 slices/dir, 4 cols each).
// 8 warps x 64 k; h/r parity double-buffered; u stays in registers.
__global__ __launch_bounds__(256, 2) void k_recur(
    const float* __restrict__ fwWg, const float* __restrict__ fwWc,
    const float* __restrict__ bwWg, const float* __restrict__ bwWc)
{
    __shared__ float Wr_s[4 * 516];
    __shared__ float Wu_s[4 * 516];
    __shared__ float Wc_s[4 * 516];
    __shared__ float redR[8 * 132];
    __shared__ float redU[8 * 132];
    __shared__ float redC[8 * 132];

    const int tid = threadIdx.x;
    const int cta = blockIdx.x;
    const int dir = cta & 1;
    const int slice = cta >> 1;   // 0..127
    const int j0 = slice * 4;
    const float* Wg = dir ? bwWg : fwWg;
    const float* Wc = dir ? bwWc : fwWc;

    for (int idx = tid; idx < 4 * 512; idx += 256) {
        int jj = idx & 3, k = idx >> 2;
        Wr_s[jj * 516 + k] = Wg[(size_t)(256 + k) * 1024 + j0 + jj];
        Wu_s[jj * 516 + k] = Wg[(size_t)(256 + k) * 1024 + 512 + j0 + jj];
        Wc_s[jj * 516 + k] = Wc[(size_t)(256 + k) * 512 + j0 + jj];
    }
    __syncthreads();

    const int warp = tid >> 5;       // 0..7
    const int b = tid & 31;
    const int k0 = warp * 64;
    const int kq0 = warp * 16;       // k-quad base
    const int prod0 = warp * 16;     // this warp's 16 producer slices
    const int col = (tid >> 5) & 3;  // epilogue/reduce mapping (tid<128)
    const int eb = tid & 31;
    const int jcol = j0 + col;
    const int hoff = (jcol >> 2) * 128 + eb * 4 + (jcol & 3);

    const float* preG = g_preG + (size_t)(dir * 128 + slice) * 512 * 8 * 32;
    const float* preC = g_preC + (size_t)(dir * 128 + slice) * 512 * 4 * 32;
    float* hQbase = g_hQ + (size_t)dir * 2 * 16384;   // + par*16384
    float* rQbase = g_rQ + (size_t)dir * 2 * 16384;
    float* outp = dir ? g_outb : g_outf;
    unsigned* fA = g_flagA[dir];
    unsigned* fB = g_flagB[dir];

    // prefetch step-0 x-projections
    float pgR = 0.f, pgU = 0.f, pcA = 0.f;
    if (tid < 128) {
        int t = dir ? 511 : 0;
        pgR = preG[((size_t)t * 8 + col) * 32 + eb];
        pgU = preG[((size_t)t * 8 + 4 + col) * 32 + eb];
        pcA = preC[((size_t)t * 4 + col) * 32 + eb];
    }

    for (int s = 0; s < 512; ++s) {
        const int t  = dir ? (511 - s) : s;
        const int tn = dir ? (510 - s) : (s + 1);
        const int wpar = s & 1;
        const int rpar = wpar ^ 1;
        float* hRd = hQbase + rpar * 16384;
        float* hWr = hQbase + wpar * 16384;
        float* rBuf = rQbase + wpar * 16384;

        // ---- per-warp wait for this warp's h producers (step s-1 done) ----
        warp_wait(fB, prod0, (unsigned)s);

        // ---- load 64-k h slice (LDG.128, operands pre-packed) + hold ----
        ull hh[32];
#pragma unroll
        for (int q = 0; q < 16; ++q)
            ldcg_v2u64(&hRd[(kq0 + q) * 128 + b * 4], hh[2 * q], hh[2 * q + 1]);
        float hold = (tid < 128) ? __ldcg(&hRd[hoff]) : 0.f;

        // ---- r GEMM (4 cols, 64 k) ----
        {
            ull acc[4];
#pragma unroll
            for (int jj = 0; jj < 4; ++jj) acc[jj] = 0ull;
#pragma unroll 4
            for (int q2 = 0; q2 < 16; ++q2) {
#pragma unroll
                for (int jj = 0; jj < 4; ++jj) {
                    ulonglong2 ww = *(const ulonglong2*)&Wr_s[jj * 516 + k0 + q2 * 4];
                    FMA2(acc[jj], hh[2 * q2],     ww.x);
                    FMA2(acc[jj], hh[2 * q2 + 1], ww.y);
                }
            }
#pragma unroll
            for (int jj = 0; jj < 4; ++jj) {
                float2 v = unpk(acc[jj]);
                redR[warp * 132 + jj * 33 + b] = v.x + v.y;
            }
        }
        __syncthreads();
        if (tid < 128) {
            float v = pgR;
#pragma unroll
            for (int q = 0; q < 8; ++q) v += redR[q * 132 + col * 33 + eb];
            __stcg(&rBuf[hoff], 1.f / (1.f + __expf(-v)));
        }
        arrive_flag(fA, slice, (unsigned)(s + 1));   // r published (syncthreads inside)

        // ---- u GEMM (hides exchange A); u stays in registers ----
        float ureg = 0.f;
        {
            ull acc[4];
#pragma unroll
            for (int jj = 0; jj < 4; ++jj) acc[jj] = 0ull;
#pragma unroll 4
            for (int q2 = 0; q2 < 16; ++q2) {
#pragma unroll
                for (int jj = 0; jj < 4; ++jj) {
                    ulonglong2 ww = *(const ulonglong2*)&Wu_s[jj * 516 + k0 + q2 * 4];
                    FMA2(acc[jj], hh[2 * q2],     ww.x);
                    FMA2(acc[jj], hh[2 * q2 + 1], ww.y);
                }
            }
#pragma unroll
            for (int jj = 0; jj < 4; ++jj) {
                float2 v = unpk(acc[jj]);
                redU[warp * 132 + jj * 33 + b] = v.x + v.y;
            }
        }
        __syncthreads();
        if (tid < 128) {
            float v = pgU;
#pragma unroll
            for (int q = 0; q < 8; ++q) v += redU[q * 132 + col * 33 + eb];
            ureg = 1.f / (1.f + __expf(-v));
            if (s < 511) {
                pgR = preG[((size_t)tn * 8 + col) * 32 + eb];
                pgU = preG[((size_t)tn * 8 + 4 + col) * 32 + eb];
            }
        }

        // ---- per-warp wait for this warp's r producers, then candidate ----
        warp_wait(fA, prod0, (unsigned)(s + 1));
        {
#pragma unroll
            for (int q = 0; q < 16; ++q) {
                ull r0, r1;
                ldcg_v2u64(&rBuf[(kq0 + q) * 128 + b * 4], r0, r1);
                MUL2(hh[2 * q],     hh[2 * q],     r0);
                MUL2(hh[2 * q + 1], hh[2 * q + 1], r1);
            }
            ull acc[4];
#pragma unroll
            for (int jj = 0; jj < 4; ++jj) acc[jj] = 0ull;
#pragma unroll 4
            for (int q2 = 0; q2 < 16; ++q2) {
#pragma unroll
                for (int jj = 0; jj < 4; ++jj) {
                    ulonglong2 ww = *(const ulonglong2*)&Wc_s[jj * 516 + k0 + q2 * 4];
                    FMA2(acc[jj], hh[2 * q2],     ww.x);
                    FMA2(acc[jj], hh[2 * q2 + 1], ww.y);
                }
            }
#pragma unroll
            for (int jj = 0; jj < 4; ++jj) {
                float2 v = unpk(acc[jj]);
                redC[warp * 132 + jj * 33 + b] = v.x + v.y;
            }
        }
        __syncthreads();
        // ---- epilogue: tanh + h update (writes parity buffer of step s) ----
        if (tid < 128) {
            float v = pcA;
#pragma unroll
            for (int q = 0; q < 8; ++q) v += redC[q * 132 + col * 33 + eb];
            float ct = tanhf(v);
            float hn = ureg * hold + (1.f - ureg) * ct;
            __stcg(&hWr[hoff], hn);
            outp[(size_t)(t * 32 + eb) * 512 + jcol] = hn;
            if (s < 511)
                pcA = preC[((size_t)tn * 4 + col) * 32 + eb];
        }
        arrive_flag(fB, slice, (unsigned)(s + 1));
    }
}

// ---------------- FC over shifted-context concat + relu + max-pool, double-buffered ----------------
__global__ __launch_bounds__(256, 2) void k_fc(const float* __restrict__ fcw,
                                               const float* __restrict__ fcb)
{
    __shared__ __align__(16) float As[2][16 * 132];
    __shared__ __align__(16) float Bs[2][16 * 132];
    const int n0 = blockIdx.x * 128;
    const int m0 = blockIdx.y * 128;
    const int tid = threadIdx.x;
    const int tx = tid & 15, ty = tid >> 4;
    const int ar0 = tid >> 2, ac0 = (tid & 3) * 4;
    const int ar1 = (tid + 256) >> 2;
    const int bk0 = tid >> 5, bn0 = (tid & 31) * 4;
    const int bk1 = (tid + 256) >> 5;

    ull acc[8][4];
#pragma unroll
    for (int i = 0; i < 8; i++)
#pragma unroll
        for (int j = 0; j < 4; j++) acc[i][j] = 0ull;

    auto gather = [&](int m, int c) -> float4 {
        float4 v = make_float4(0.f, 0.f, 0.f, 0.f);
        if (c < 512) {
            if (m >= 32) v = *(const float4*)&g_outf[(size_t)(m - 32) * 512 + c];
        } else if (c < 768) {
            v = *(const float4*)&g_xt[(size_t)m * 256 + (c - 512)];
        } else {
            if (m < 16352) v = *(const float4*)&g_outb[(size_t)(m + 32) * 512 + (c - 768)];
        }
        return v;
    };

    float4 pa0, pa1, pb0, pb1;
    pa0 = gather(m0 + ar0, ac0);
    pa1 = gather(m0 + ar1, ac0);
    pb0 = *(const float4*)&fcw[(size_t)bk0 * 512 + n0 + bn0];
    pb1 = *(const float4*)&fcw[(size_t)bk1 * 512 + n0 + bn0];
    {
        As[0][(ac0 + 0) * 132 + ar0] = pa0.x; As[0][(ac0 + 1) * 132 + ar0] = pa0.y;
        As[0][(ac0 + 2) * 132 + ar0] = pa0.z; As[0][(ac0 + 3) * 132 + ar0] = pa0.w;
        As[0][(ac0 + 0) * 132 + ar1] = pa1.x; As[0][(ac0 + 1) * 132 + ar1] = pa1.y;
        As[0][(ac0 + 2) * 132 + ar1] = pa1.z; As[0][(ac0 + 3) * 132 + ar1] = pa1.w;
        *(float4*)&Bs[0][bk0 * 132 + bn0] = pb0;
        *(float4*)&Bs[0][bk1 * 132 + bn0] = pb1;
    }
    __syncthreads();
    int p = 0;
    for (int slab = 0; slab < 80; ++slab) {
        if (slab < 79) {
            int k0 = (slab + 1) * 16;
            pa0 = gather(m0 + ar0, k0 + ac0);
            pa1 = gather(m0 + ar1, k0 + ac0);
            pb0 = *(const float4*)&fcw[(size_t)(k0 + bk0) * 512 + n0 + bn0];
            pb1 = *(const float4*)&fcw[(size_t)(k0 + bk1) * 512 + n0 + bn0];
        }
#pragma unroll
        for (int kk = 0; kk < 16; ++kk) {
            float4 a0 = *(const float4*)&As[p][kk * 132 + ty * 8];
            float4 a1 = *(const float4*)&As[p][kk * 132 + ty * 8 + 4];
            ulonglong2 w01 = *(const ulonglong2*)&Bs[p][kk * 132 + tx * 8];
            ulonglong2 w23 = *(const ulonglong2*)&Bs[p][kk * 132 + tx * 8 + 4];
            ull ad[8];
            ad[0] = dup2f(a0.x); ad[1] = dup2f(a0.y); ad[2] = dup2f(a0.z); ad[3] = dup2f(a0.w);
            ad[4] = dup2f(a1.x); ad[5] = dup2f(a1.y); ad[6] = dup2f(a1.z); ad[7] = dup2f(a1.w);
#pragma unroll
            for (int i = 0; i < 8; i++) {
                FMA2(acc[i][0], ad[i], w01.x);
                FMA2(acc[i][1], ad[i], w01.y);
                FMA2(acc[i][2], ad[i], w23.x);
                FMA2(acc[i][3], ad[i], w23.y);
            }
        }
        if (slab < 79) {
            int q = p ^ 1;
            As[q][(ac0 + 0) * 132 + ar0] = pa0.x; As[q][(ac0 + 1) * 132 + ar0] = pa0.y;
            As[q][(ac0 + 2) * 132 + ar0] = pa0.z; As[q][(ac0 + 3) * 132 + ar0] = pa0.w;
            As[q][(ac0 + 0) * 132 + ar1] = pa1.x; As[q][(ac0 + 1) * 132 + ar1] = pa1.y;
            As[q][(ac0 + 2) * 132 + ar1] = pa1.z; As[q][(ac0 + 3) * 132 + ar1] = pa1.w;
            *(float4*)&Bs[q][bk0 * 132 + bn0] = pb0;
            *(float4*)&Bs[q][bk1 * 132 + bn0] = pb1;
            __syncthreads();
            p = q;
        }
    }
    float4 bb0 = *(const float4*)&fcb[n0 + tx * 8];
    float4 bb1 = *(const float4*)&fcb[n0 + tx * 8 + 4];
    float bcol[8] = {bb0.x, bb0.y, bb0.z, bb0.w, bb1.x, bb1.y, bb1.z, bb1.w};
#pragma unroll
    for (int i = 0; i < 8; i++) {
        int m = m0 + ty * 8 + i;
        int bb = m & 31;
        int base = bb * 512 + n0 + tx * 8;
#pragma unroll
        for (int j = 0; j < 4; j++) {
            float2 v = unpk(acc[i][j]);
            float r0 = fmaxf(v.x + bcol[2 * j], 0.f);
            float r1 = fmaxf(v.y + bcol[2 * j + 1], 0.f);
            atomicMax((int*)&g_pool[base + 2 * j + 0], __float_as_int(r0));
            atomicMax((int*)&g_pool[base + 2 * j + 1], __float_as_int(r1));
        }
    }
}

// ---------------- MLP head ----------------
__global__ void k_mlp(const float* __restrict__ mw, const float* __restrict__ mb,
                      float* __restrict__ out)
{
    __shared__ float sp[512];
    int bb = blockIdx.x;
    int tid = threadIdx.x;
    for (int i = tid; i < 512; i += 256) sp[i] = g_pool[bb * 512 + i];
    __syncthreads();
    float acc = mb[tid];
#pragma unroll 8
    for (int h = 0; h < 512; ++h) acc += sp[h] * mw[h * 256 + tid];
    out[bb * 256 + tid] = acc;
}

// ---------------- launch ----------------
extern "C" void kernel_launch(void* const* d_in, const int* in_sizes, int n_in,
                              void* d_out, int out_size)
{
    const float* x    = (const float*)d_in[0];
    const float* fwWg = (const float*)d_in[1];
    const float* fwbg = (const float*)d_in[2];
    const float* fwWc = (const float*)d_in[3];
    const float* fwbc = (const float*)d_in[4];
    const float* bwWg = (const float*)d_in[5];
    const float* bwbg = (const float*)d_in[6];
    const float* bwWc = (const float*)d_in[7];
    const float* bwbc = (const float*)d_in[8];
    const float* fcw  = (const float*)d_in[9];
    const float* fcb  = (const float*)d_in[10];
    const float* mw   = (const float*)d_in[11];
    const float* mb   = (const float*)d_in[12];
    float* out = (float*)d_out;

    k_init<<<256, 256>>>();
    k_xcopy<<<4096, 256>>>(x);
    k_gemm_pre<<<dim3(24, 128), 256>>>(x, fwWg, fwbg, fwWc, fwbc, bwWg, bwbg, bwWc, bwbc);
    k_recur<<<256, 256>>>(fwWg, fwWc, bwWg, bwWc);
    k_fc<<<dim3(4, 128), 256>>>(fcw, fcb);
    k_mlp<<<32, 256>>>(mw, mb, out);
}

// round 12
// speedup vs baseline: 1.8241x; 1.8241x over previous
#include <cuda_runtime.h>
#include <math.h>

typedef unsigned long long ull;

#define FMA2(d, a, b) asm("fma.rn.f32x2 %0, %1, %2, %0;" : "+l"(d) : "l"(a), "l"(b))
#define MUL2(d, a, b) asm("mul.rn.f32x2 %0, %1, %2;" : "=l"(d) : "l"(a), "l"(b))

__device__ __forceinline__ ull dup2f(float a) {
    ull r; asm("mov.b64 %0, {%1, %1};" : "=l"(r) : "f"(a)); return r;
}
__device__ __forceinline__ float2 unpk(ull v) {
    float2 f; asm("mov.b64 {%0, %1}, %2;" : "=f"(f.x), "=f"(f.y) : "l"(v)); return f;
}
// 128-bit L2 load: two packed f32x2 operands in one LDG.128
__device__ __forceinline__ void ldcg_v2u64(const float* p, ull& lo, ull& hi) {
    asm volatile("ld.global.cg.v2.u64 {%0, %1}, [%2];" : "=l"(lo), "=l"(hi) : "l"(p));
}
__device__ __forceinline__ unsigned acq_load(const unsigned* p) {
    unsigned v;
    asm volatile("ld.acquire.gpu.global.u32 %0, [%1];" : "=r"(v) : "l"(p) : "memory");
    return v;
}

// ---------------- device scratch ----------------
// gate pre [dir*64+c64][t][16][32] : sub 0..7 = r cols (c64*8+j), 8..15 = u cols
__device__ float g_preG[(size_t)2 * 64 * 512 * 16 * 32];
__device__ float g_preC[(size_t)2 * 64 * 512 * 8 * 32];
__device__ float g_xt [(size_t)512 * 32 * 256];  // x: [t][b][c]
__device__ float g_outf[(size_t)512 * 32 * 512]; // fw hidden [t][b][h]
__device__ float g_outb[(size_t)512 * 32 * 512]; // bw hidden [t][b][h]
// h quad-interleaved, PARITY double-buffered: [dir][par][kquad 128][b 32][4]
__device__ float g_hQ [2 * 2 * 128 * 32 * 4];
// rh (= r * h_prev) quad-interleaved, parity double-buffered, same layout
__device__ float g_rQ [2 * 2 * 128 * 32 * 4];
__device__ float g_pool[32 * 512];
// distributed flags: one padded word per CTA (128B apart), per direction/phase
__device__ unsigned g_flagA[2][64 * 32];
__device__ unsigned g_flagB[2][64 * 32];

// ---------------- init ----------------
__global__ void k_init() {
    int i = blockIdx.x * blockDim.x + threadIdx.x;   // 65536 threads
    if (i < 2 * 2 * 128 * 32 * 4) { g_hQ[i] = 0.f; g_rQ[i] = 0.f; }
    if (i < 32 * 512) g_pool[i] = 0.f;
    if (i < 2 * 64 * 32) { ((unsigned*)g_flagA)[i] = 0u; ((unsigned*)g_flagB)[i] = 0u; }
}

// ---------------- x -> [t][b][c] copy ----------------
__global__ void k_xcopy(const float* __restrict__ x) {
    int idx = blockIdx.x * blockDim.x + threadIdx.x;  // float4 id
    if (idx < 32 * 512 * 64) {
        int row = idx >> 6, c4 = idx & 63;            // row = b*512 + t
        int b = row >> 9, t = row & 511;
        ((float4*)g_xt)[(size_t)(t * 32 + b) * 64 + c4] = ((const float4*)x)[idx];
    }
}

// ---------------- GEMM1: x-part projections (M=16384,K=256,N=3072), double-buffered ----------------
__global__ __launch_bounds__(256, 2) void k_gemm_pre(
    const float* __restrict__ x,
    const float* __restrict__ fwWg, const float* __restrict__ fwbg,
    const float* __restrict__ fwWc, const float* __restrict__ fwbc,
    const float* __restrict__ bwWg, const float* __restrict__ bwbg,
    const float* __restrict__ bwWc, const float* __restrict__ bwbc)
{
    __shared__ __align__(16) float As[2][16 * 132];
    __shared__ __align__(16) float Bs[2][16 * 132];
    const int n0 = blockIdx.x * 128;
    const int m0 = blockIdx.y * 128;
    const float* W; const float* bias; int ld, nrel, dir, isC;
    if (n0 < 1024)      { W = fwWg; bias = fwbg; ld = 1024; nrel = n0;        dir = 0; isC = 0; }
    else if (n0 < 1536) { W = fwWc; bias = fwbc; ld = 512;  nrel = n0 - 1024; dir = 0; isC = 1; }
    else if (n0 < 2560) { W = bwWg; bias = bwbg; ld = 1024; nrel = n0 - 1536; dir = 1; isC = 0; }
    else                { W = bwWc; bias = bwbc; ld = 512;  nrel = n0 - 2560; dir = 1; isC = 1; }
    const int tid = threadIdx.x;
    const int tx = tid & 15, ty = tid >> 4;
    const int ar0 = tid >> 2, ac0 = (tid & 3) * 4;
    const int ar1 = (tid + 256) >> 2;
    const int bk0 = tid >> 5, bn0 = (tid & 31) * 4;
    const int bk1 = (tid + 256) >> 5;

    ull acc[8][4];
#pragma unroll
    for (int i = 0; i < 8; i++)
#pragma unroll
        for (int j = 0; j < 4; j++) acc[i][j] = 0ull;

    float4 pa0, pa1, pb0, pb1;
    pa0 = *(const float4*)&x[(size_t)(m0 + ar0) * 256 + ac0];
    pa1 = *(const float4*)&x[(size_t)(m0 + ar1) * 256 + ac0];
    pb0 = *(const float4*)&W[(size_t)bk0 * ld + nrel + bn0];
    pb1 = *(const float4*)&W[(size_t)bk1 * ld + nrel + bn0];
    {
        As[0][(ac0 + 0) * 132 + ar0] = pa0.x; As[0][(ac0 + 1) * 132 + ar0] = pa0.y;
        As[0][(ac0 + 2) * 132 + ar0] = pa0.z; As[0][(ac0 + 3) * 132 + ar0] = pa0.w;
        As[0][(ac0 + 0) * 132 + ar1] = pa1.x; As[0][(ac0 + 1) * 132 + ar1] = pa1.y;
        As[0][(ac0 + 2) * 132 + ar1] = pa1.z; As[0][(ac0 + 3) * 132 + ar1] = pa1.w;
        *(float4*)&Bs[0][bk0 * 132 + bn0] = pb0;
        *(float4*)&Bs[0][bk1 * 132 + bn0] = pb1;
    }
    __syncthreads();
    int p = 0;
    for (int slab = 0; slab < 16; ++slab) {
        if (slab < 15) {
            int k0 = (slab + 1) * 16;
            pa0 = *(const float4*)&x[(size_t)(m0 + ar0) * 256 + k0 + ac0];
            pa1 = *(const float4*)&x[(size_t)(m0 + ar1) * 256 + k0 + ac0];
            pb0 = *(const float4*)&W[(size_t)(k0 + bk0) * ld + nrel + bn0];
            pb1 = *(const float4*)&W[(size_t)(k0 + bk1) * ld + nrel + bn0];
        }
#pragma unroll
        for (int kk = 0; kk < 16; ++kk) {
            float4 a0 = *(const float4*)&As[p][kk * 132 + ty * 8];
            float4 a1 = *(const float4*)&As[p][kk * 132 + ty * 8 + 4];
            ulonglong2 w01 = *(const ulonglong2*)&Bs[p][kk * 132 + tx * 8];
            ulonglong2 w23 = *(const ulonglong2*)&Bs[p][kk * 132 + tx * 8 + 4];
            ull ad[8];
            ad[0] = dup2f(a0.x); ad[1] = dup2f(a0.y); ad[2] = dup2f(a0.z); ad[3] = dup2f(a0.w);
            ad[4] = dup2f(a1.x); ad[5] = dup2f(a1.y); ad[6] = dup2f(a1.z); ad[7] = dup2f(a1.w);
#pragma unroll
            for (int i = 0; i < 8; i++) {
                FMA2(acc[i][0], ad[i], w01.x);
                FMA2(acc[i][1], ad[i], w01.y);
                FMA2(acc[i][2], ad[i], w23.x);
                FMA2(acc[i][3], ad[i], w23.y);
            }
        }
        if (slab < 15) {
            int q = p ^ 1;
            As[q][(ac0 + 0) * 132 + ar0] = pa0.x; As[q][(ac0 + 1) * 132 + ar0] = pa0.y;
            As[q][(ac0 + 2) * 132 + ar0] = pa0.z; As[q][(ac0 + 3) * 132 + ar0] = pa0.w;
            As[q][(ac0 + 0) * 132 + ar1] = pa1.x; As[q][(ac0 + 1) * 132 + ar1] = pa1.y;
            As[q][(ac0 + 2) * 132 + ar1] = pa1.z; As[q][(ac0 + 3) * 132 + ar1] = pa1.w;
            *(float4*)&Bs[q][bk0 * 132 + bn0] = pb0;
            *(float4*)&Bs[q][bk1 * 132 + bn0] = pb1;
            __syncthreads();
            p = q;
        }
    }
    float4 bb0 = *(const float4*)&bias[nrel + tx * 8];
    float4 bb1 = *(const float4*)&bias[nrel + tx * 8 + 4];
    float bcol[8] = {bb0.x, bb0.y, bb0.z, bb0.w, bb1.x, bb1.y, bb1.z, bb1.w};
    const int cbase = nrel + tx * 8;
#pragma unroll
    for (int i = 0; i < 8; i++) {
        int m = m0 + ty * 8 + i;
        int t = m & 511, bb = m >> 9;
        float vals[8];
#pragma unroll
        for (int j = 0; j < 4; j++) {
            float2 v = unpk(acc[i][j]);
            vals[2 * j] = v.x + bcol[2 * j];
            vals[2 * j + 1] = v.y + bcol[2 * j + 1];
        }
        if (!isC) {
            int c, sub0;
            if (cbase < 512) { c = cbase >> 3; sub0 = 0; }
            else             { c = (cbase - 512) >> 3; sub0 = 8; }
            float* dst = &g_preG[(((size_t)(dir * 64 + c) * 512 + t) * 16 + sub0) * 32 + bb];
#pragma unroll
            for (int cc = 0; cc < 8; ++cc) dst[cc * 32] = vals[cc];
        } else {
            int c = cbase >> 3;
            float* dst = &g_preC[(((size_t)(dir * 64 + c) * 512 + t) * 8) * 32 + bb];
#pragma unroll
            for (int cc = 0; cc < 8; ++cc) dst[cc * 32] = vals[cc];
        }
    }
}

// ---------------- flag publish (CTA-wide) + per-warp consumer wait ----------------
__device__ __forceinline__ void arrive_flag(unsigned* flag, int c64, unsigned val) {
    __syncthreads();
    if (threadIdx.x == 0) {
        __threadfence();
        *(volatile unsigned*)&flag[c64 * 32] = val;
    }
}
// warp waits only on its 4 producer CTAs (cols 32w..32w+32 -> CTAs 4w..4w+3)
__device__ __forceinline__ void warp_wait(const unsigned* flag, int prod0, unsigned target) {
    int lane = threadIdx.x & 31;
    if (lane < 4) {
        const unsigned* fp = &flag[(prod0 + lane) * 32];
        while (acq_load(fp) < target) { }
    }
    __syncwarp();
}

// ---------------- persistent bidirectional GRU ----------------
// 128 CTAs x 512 threads: dir = cta>>6, c64 = cta&63. CTA owns cols [c64*8, c64*8+8).
// Per-warp producer flags; h and rh parity double-buffered; u stays in registers.
// Producers publish rh = r * h_prev directly (consumer-side multiply eliminated).
__global__ __launch_bounds__(512, 1) void k_recur(
    const float* __restrict__ fwWg, const float* __restrict__ fwWc,
    const float* __restrict__ bwWg, const float* __restrict__ bwWc)
{
    extern __shared__ float sm[];
    float* Wr_s = sm;              // 8 x 516
    float* Wu_s = sm + 4128;       // 8 x 516
    float* Wc_s = sm + 8256;       // 8 x 516
    float* redR = sm + 12384;      // 16 warps x 8 cols x 33
    float* redU = sm + 16608;
    float* redC = sm + 20832;

    const int tid = threadIdx.x;
    const int cta = blockIdx.x;
    const int dir = cta >> 6;
    const int c64 = cta & 63;
    const int j0 = c64 * 8;
    const float* Wg = dir ? bwWg : fwWg;
    const float* Wc = dir ? bwWc : fwWc;

    for (int idx = tid; idx < 8 * 512; idx += 512) {
        int jj = idx & 7, k = idx >> 3;
        Wr_s[jj * 516 + k] = Wg[(size_t)(256 + k) * 1024 + j0 + jj];
        Wu_s[jj * 516 + k] = Wg[(size_t)(256 + k) * 1024 + 512 + j0 + jj];
        Wc_s[jj * 516 + k] = Wc[(size_t)(256 + k) * 512 + j0 + jj];
    }
    __syncthreads();

    const int warp = tid >> 5;
    const int b = tid & 31;
    const int k0 = warp * 32;        // 16 warps x 32 k
    const int kq0 = warp * 8;        // k-quad base
    const int prod0 = warp * 4;      // this warp's 4 producer CTAs
    const int col = (tid >> 5) & 7;  // epilogue/reduce mapping (tid<256)
    const int eb = tid & 31;
    const int jcol = j0 + col;
    const int hoff = (jcol >> 2) * 128 + eb * 4 + (jcol & 3);

    const float* preG = g_preG + (size_t)(dir * 64 + c64) * 512 * 16 * 32;
    const float* preC = g_preC + (size_t)(dir * 64 + c64) * 512 * 8 * 32;
    float* hQbase = g_hQ + (size_t)dir * 2 * 16384;   // + par*16384
    float* rQbase = g_rQ + (size_t)dir * 2 * 16384;
    float* outp = dir ? g_outb : g_outf;
    unsigned* fA = g_flagA[dir];
    unsigned* fB = g_flagB[dir];

    // prefetch step-0 x-projections
    float pgR = 0.f, pgU = 0.f, pcA = 0.f;
    if (tid < 256) {
        int t = dir ? 511 : 0;
        pgR = preG[((size_t)t * 16 + col) * 32 + eb];
        pgU = preG[((size_t)t * 16 + 8 + col) * 32 + eb];
        pcA = preC[((size_t)t * 8 + col) * 32 + eb];
    }

    for (int s = 0; s < 512; ++s) {
        const int t  = dir ? (511 - s) : s;
        const int tn = dir ? (510 - s) : (s + 1);
        const int wpar = s & 1;          // write parity (state s)
        const int rpar = wpar ^ 1;       // read parity (state s-1)
        float* hRd = hQbase + rpar * 16384;
        float* hWr = hQbase + wpar * 16384;
        float* rBuf = rQbase + wpar * 16384;

        // ---- per-warp wait for this warp's h producers (step s-1 done) ----
        warp_wait(fB, prod0, (unsigned)s);

        // ---- load h slice (LDG.128, operands pre-packed) + hold ----
        ull hh[16];
#pragma unroll
        for (int q = 0; q < 8; ++q)
            ldcg_v2u64(&hRd[(kq0 + q) * 128 + b * 4], hh[2 * q], hh[2 * q + 1]);
        float hold = (tid < 256) ? __ldcg(&hRd[hoff]) : 0.f;

        // ---- r GEMM ----
        {
            ull acc[8];
#pragma unroll
            for (int jj = 0; jj < 8; ++jj) acc[jj] = 0ull;
#pragma unroll
            for (int q2 = 0; q2 < 8; ++q2) {
#pragma unroll
                for (int jj = 0; jj < 8; ++jj) {
                    ulonglong2 ww = *(const ulonglong2*)&Wr_s[jj * 516 + k0 + q2 * 4];
                    FMA2(acc[jj], hh[2 * q2],     ww.x);
                    FMA2(acc[jj], hh[2 * q2 + 1], ww.y);
                }
            }
#pragma unroll
            for (int jj = 0; jj < 8; ++jj) {
                float2 v = unpk(acc[jj]);
                redR[warp * 264 + jj * 33 + b] = v.x + v.y;
            }
        }
        __syncthreads();
        if (tid < 256) {
            float v = pgR;
#pragma unroll
            for (int q = 0; q < 16; ++q) v += redR[q * 264 + col * 33 + eb];
            float rv = 1.f / (1.f + __expf(-v));
            __stcg(&rBuf[hoff], rv * hold);   // publish rh directly
        }
        arrive_flag(fA, c64, (unsigned)(s + 1));   // rh published (syncthreads inside)

        // ---- u GEMM (no new data; hides exchange A); u stays in registers ----
        float ureg = 0.f;
        {
            ull acc[8];
#pragma unroll
            for (int jj = 0; jj < 8; ++jj) acc[jj] = 0ull;
#pragma unroll
            for (int q2 = 0; q2 < 8; ++q2) {
#pragma unroll
                for (int jj = 0; jj < 8; ++jj) {
                    ulonglong2 ww = *(const ulonglong2*)&Wu_s[jj * 516 + k0 + q2 * 4];
                    FMA2(acc[jj], hh[2 * q2],     ww.x);
                    FMA2(acc[jj], hh[2 * q2 + 1], ww.y);
                }
            }
#pragma unroll
            for (int jj = 0; jj < 8; ++jj) {
                float2 v = unpk(acc[jj]);
                redU[warp * 264 + jj * 33 + b] = v.x + v.y;
            }
        }
        __syncthreads();
        if (tid < 256) {
            float v = pgU;
#pragma unroll
            for (int q = 0; q < 16; ++q) v += redU[q * 264 + col * 33 + eb];
            ureg = 1.f / (1.f + __expf(-v));
            if (s < 511) {
                pgR = preG[((size_t)tn * 16 + col) * 32 + eb];
                pgU = preG[((size_t)tn * 16 + 8 + col) * 32 + eb];
            }
        }

        // ---- per-warp wait for this warp's rh producers, then candidate ----
        warp_wait(fA, prod0, (unsigned)(s + 1));
        {
#pragma unroll
            for (int q = 0; q < 8; ++q)
                ldcg_v2u64(&rBuf[(kq0 + q) * 128 + b * 4], hh[2 * q], hh[2 * q + 1]);
            ull acc[8];
#pragma unroll
            for (int jj = 0; jj < 8; ++jj) acc[jj] = 0ull;
#pragma unroll
            for (int q2 = 0; q2 < 8; ++q2) {
#pragma unroll
                for (int jj = 0; jj < 8; ++jj) {
                    ulonglong2 ww = *(const ulonglong2*)&Wc_s[jj * 516 + k0 + q2 * 4];
                    FMA2(acc[jj], hh[2 * q2],     ww.x);
                    FMA2(acc[jj], hh[2 * q2 + 1], ww.y);
                }
            }
#pragma unroll
            for (int jj = 0; jj < 8; ++jj) {
                float2 v = unpk(acc[jj]);
                redC[warp * 264 + jj * 33 + b] = v.x + v.y;
            }
        }
        __syncthreads();
        // ---- epilogue: tanh + h update (writes parity buffer of step s) ----
        if (tid < 256) {
            float v = pcA;
#pragma unroll
            for (int q = 0; q < 16; ++q) v += redC[q * 264 + col * 33 + eb];
            float ct = tanhf(v);
            float hn = ureg * hold + (1.f - ureg) * ct;
            __stcg(&hWr[hoff], hn);
            outp[(size_t)(t * 32 + eb) * 512 + jcol] = hn;
            if (s < 511)
                pcA = preC[((size_t)tn * 8 + col) * 32 + eb];
        }
        arrive_flag(fB, c64, (unsigned)(s + 1));
    }
}

// ---------------- FC over shifted-context concat + relu + max-pool, double-buffered ----------------
__global__ __launch_bounds__(256, 2) void k_fc(const float* __restrict__ fcw,
                                               const float* __restrict__ fcb)
{
    __shared__ __align__(16) float As[2][16 * 132];
    __shared__ __align__(16) float Bs[2][16 * 132];
    const int n0 = blockIdx.x * 128;
    const int m0 = blockIdx.y * 128;
    const int tid = threadIdx.x;
    const int tx = tid & 15, ty = tid >> 4;
    const int ar0 = tid >> 2, ac0 = (tid & 3) * 4;
    const int ar1 = (tid + 256) >> 2;
    const int bk0 = tid >> 5, bn0 = (tid & 31) * 4;
    const int bk1 = (tid + 256) >> 5;

    ull acc[8][4];
#pragma unroll
    for (int i = 0; i < 8; i++)
#pragma unroll
        for (int j = 0; j < 4; j++) acc[i][j] = 0ull;

    auto gather = [&](int m, int c) -> float4 {
        float4 v = make_float4(0.f, 0.f, 0.f, 0.f);
        if (c < 512) {
            if (m >= 32) v = *(const float4*)&g_outf[(size_t)(m - 32) * 512 + c];
        } else if (c < 768) {
            v = *(const float4*)&g_xt[(size_t)m * 256 + (c - 512)];
        } else {
            if (m < 16352) v = *(const float4*)&g_outb[(size_t)(m + 32) * 512 + (c - 768)];
        }
        return v;
    };

    float4 pa0, pa1, pb0, pb1;
    pa0 = gather(m0 + ar0, ac0);
    pa1 = gather(m0 + ar1, ac0);
    pb0 = *(const float4*)&fcw[(size_t)bk0 * 512 + n0 + bn0];
    pb1 = *(const float4*)&fcw[(size_t)bk1 * 512 + n0 + bn0];
    {
        As[0][(ac0 + 0) * 132 + ar0] = pa0.x; As[0][(ac0 + 1) * 132 + ar0] = pa0.y;
        As[0][(ac0 + 2) * 132 + ar0] = pa0.z; As[0][(ac0 + 3) * 132 + ar0] = pa0.w;
        As[0][(ac0 + 0) * 132 + ar1] = pa1.x; As[0][(ac0 + 1) * 132 + ar1] = pa1.y;
        As[0][(ac0 + 2) * 132 + ar1] = pa1.z; As[0][(ac0 + 3) * 132 + ar1] = pa1.w;
        *(float4*)&Bs[0][bk0 * 132 + bn0] = pb0;
        *(float4*)&Bs[0][bk1 * 132 + bn0] = pb1;
    }
    __syncthreads();
    int p = 0;
    for (int slab = 0; slab < 80; ++slab) {
        if (slab < 79) {
            int k0 = (slab + 1) * 16;
            pa0 = gather(m0 + ar0, k0 + ac0);
            pa1 = gather(m0 + ar1, k0 + ac0);
            pb0 = *(const float4*)&fcw[(size_t)(k0 + bk0) * 512 + n0 + bn0];
            pb1 = *(const float4*)&fcw[(size_t)(k0 + bk1) * 512 + n0 + bn0];
        }
#pragma unroll
        for (int kk = 0; kk < 16; ++kk) {
            float4 a0 = *(const float4*)&As[p][kk * 132 + ty * 8];
            float4 a1 = *(const float4*)&As[p][kk * 132 + ty * 8 + 4];
            ulonglong2 w01 = *(const ulonglong2*)&Bs[p][kk * 132 + tx * 8];
            ulonglong2 w23 = *(const ulonglong2*)&Bs[p][kk * 132 + tx * 8 + 4];
            ull ad[8];
            ad[0] = dup2f(a0.x); ad[1] = dup2f(a0.y); ad[2] = dup2f(a0.z); ad[3] = dup2f(a0.w);
            ad[4] = dup2f(a1.x); ad[5] = dup2f(a1.y); ad[6] = dup2f(a1.z); ad[7] = dup2f(a1.w);
#pragma unroll
            for (int i = 0; i < 8; i++) {
                FMA2(acc[i][0], ad[i], w01.x);
                FMA2(acc[i][1], ad[i], w01.y);
                FMA2(acc[i][2], ad[i], w23.x);
                FMA2(acc[i][3], ad[i], w23.y);
            }
        }
        if (slab < 79) {
            int q = p ^ 1;
            As[q][(ac0 + 0) * 132 + ar0] = pa0.x; As[q][(ac0 + 1) * 132 + ar0] = pa0.y;
            As[q][(ac0 + 2) * 132 + ar0] = pa0.z; As[q][(ac0 + 3) * 132 + ar0] = pa0.w;
            As[q][(ac0 + 0) * 132 + ar1] = pa1.x; As[q][(ac0 + 1) * 132 + ar1] = pa1.y;
            As[q][(ac0 + 2) * 132 + ar1] = pa1.z; As[q][(ac0 + 3) * 132 + ar1] = pa1.w;
            *(float4*)&Bs[q][bk0 * 132 + bn0] = pb0;
            *(float4*)&Bs[q][bk1 * 132 + bn0] = pb1;
            __syncthreads();
            p = q;
        }
    }
    float4 bb0 = *(const float4*)&fcb[n0 + tx * 8];
    float4 bb1 = *(const float4*)&fcb[n0 + tx * 8 + 4];
    float bcol[8] = {bb0.x, bb0.y, bb0.z, bb0.w, bb1.x, bb1.y, bb1.z, bb1.w};
#pragma unroll
    for (int i = 0; i < 8; i++) {
        int m = m0 + ty * 8 + i;
        int bb = m & 31;
        int base = bb * 512 + n0 + tx * 8;
#pragma unroll
        for (int j = 0; j < 4; j++) {
            float2 v = unpk(acc[i][j]);
            float r0 = fmaxf(v.x + bcol[2 * j], 0.f);
            float r1 = fmaxf(v.y + bcol[2 * j + 1], 0.f);
            atomicMax((int*)&g_pool[base + 2 * j + 0], __float_as_int(r0));
            atomicMax((int*)&g_pool[base + 2 * j + 1], __float_as_int(r1));
        }
    }
}

// ---------------- MLP head ----------------
__global__ void k_mlp(const float* __restrict__ mw, const float* __restrict__ mb,
                      float* __restrict__ out)
{
    __shared__ float sp[512];
    int bb = blockIdx.x;
    int tid = threadIdx.x;
    for (int i = tid; i < 512; i += 256) sp[i] = g_pool[bb * 512 + i];
    __syncthreads();
    float acc = mb[tid];
#pragma unroll 8
    for (int h = 0; h < 512; ++h) acc += sp[h] * mw[h * 256 + tid];
    out[bb * 256 + tid] = acc;
}

// ---------------- launch ----------------
extern "C" void kernel_launch(void* const* d_in, const int* in_sizes, int n_in,
                              void* d_out, int out_size)
{
    const float* x    = (const float*)d_in[0];
    const float* fwWg = (const float*)d_in[1];
    const float* fwbg = (const float*)d_in[2];
    const float* fwWc = (const float*)d_in[3];
    const float* fwbc = (const float*)d_in[4];
    const float* bwWg = (const float*)d_in[5];
    const float* bwbg = (const float*)d_in[6];
    const float* bwWc = (const float*)d_in[7];
    const float* bwbc = (const float*)d_in[8];
    const float* fcw  = (const float*)d_in[9];
    const float* fcb  = (const float*)d_in[10];
    const float* mw   = (const float*)d_in[11];
    const float* mb   = (const float*)d_in[12];
    float* out = (float*)d_out;

    cudaFuncSetAttribute(k_recur, cudaFuncAttributeMaxDynamicSharedMemorySize, 100352);

    k_init<<<256, 256>>>();
    k_xcopy<<<4096, 256>>>(x);
    k_gemm_pre<<<dim3(24, 128), 256>>>(x, fwWg, fwbg, fwWc, fwbc, bwWg, bwbg, bwWc, bwbc);
    k_recur<<<128, 512, 100352>>>(fwWg, fwWc, bwWg, bwWc);
    k_fc<<<dim3(4, 128), 256>>>(fcw, fcb);
    k_mlp<<<32, 256>>>(mw, mb, out);
}

// round 13
// speedup vs baseline: 2.0471x; 1.1223x over previous
#include <cuda_runtime.h>
#include <math.h>

typedef unsigned long long ull;

#define FMA2(d, a, b) asm("fma.rn.f32x2 %0, %1, %2, %0;" : "+l"(d) : "l"(a), "l"(b))

__device__ __forceinline__ float2 unpk(ull v) {
    float2 f; asm("mov.b64 {%0, %1}, %2;" : "=f"(f.x), "=f"(f.y) : "l"(v)); return f;
}
__device__ __forceinline__ ull dup2f(float a) {
    ull r; asm("mov.b64 %0, {%1, %1};" : "=l"(r) : "f"(a)); return r;
}
// 128-bit L2 load: two packed f32x2 operands in one LDG.128
__device__ __forceinline__ void ldcg_v2u64(const float* p, ull& lo, ull& hi) {
    asm volatile("ld.global.cg.v2.u64 {%0, %1}, [%2];" : "=l"(lo), "=l"(hi) : "l"(p));
}
__device__ __forceinline__ unsigned acq_load(const unsigned* p) {
    unsigned v;
    asm volatile("ld.acquire.gpu.global.u32 %0, [%1];" : "=r"(v) : "l"(p) : "memory");
    return v;
}

// ---------------- device scratch ----------------
__device__ float g_xt [(size_t)512 * 32 * 256];  // x: [t][b][c]       (for FC)
__device__ float g_xQ [(size_t)512 * 64 * 32 * 4]; // x quad: [t][kq][b][4] (for recur)
__device__ float g_outf[(size_t)512 * 32 * 512]; // fw hidden [t][b][h]
__device__ float g_outb[(size_t)512 * 32 * 512]; // bw hidden [t][b][h]
// h quad-interleaved, PARITY double-buffered: [dir][par][kquad 128][b 32][4]
__device__ float g_hQ [2 * 2 * 128 * 32 * 4];
// rh (= r * h_prev) quad-interleaved, parity double-buffered, same layout
__device__ float g_rQ [2 * 2 * 128 * 32 * 4];
__device__ float g_pool[32 * 512];
// distributed flags: one padded word per CTA (128B apart), per direction/phase
__device__ unsigned g_flagA[2][64 * 32];
__device__ unsigned g_flagB[2][64 * 32];

// ---------------- init ----------------
__global__ void k_init() {
    int i = blockIdx.x * blockDim.x + threadIdx.x;   // 65536 threads
    if (i < 2 * 2 * 128 * 32 * 4) { g_hQ[i] = 0.f; g_rQ[i] = 0.f; }
    if (i < 32 * 512) g_pool[i] = 0.f;
    if (i < 2 * 64 * 32) { ((unsigned*)g_flagA)[i] = 0u; ((unsigned*)g_flagB)[i] = 0u; }
}

// ---------------- x -> [t][b][c] and quad layouts ----------------
__global__ void k_xcopy(const float* __restrict__ x) {
    int idx = blockIdx.x * blockDim.x + threadIdx.x;  // float4 id
    if (idx < 32 * 512 * 64) {
        int row = idx >> 6, c4 = idx & 63;            // row = b*512 + t
        int b = row >> 9, t = row & 511;
        float4 v = ((const float4*)x)[idx];
        ((float4*)g_xt)[(size_t)(t * 32 + b) * 64 + c4] = v;
        ((float4*)g_xQ)[((size_t)t * 64 + c4) * 32 + b] = v;
    }
}

// ---------------- flag publish (CTA-wide) + per-warp consumer wait ----------------
__device__ __forceinline__ void arrive_flag(unsigned* flag, int c64, unsigned val) {
    __syncthreads();
    if (threadIdx.x == 0) {
        __threadfence();
        *(volatile unsigned*)&flag[c64 * 32] = val;
    }
}
// warp waits only on its 4 producer CTAs (cols 32w..32w+32 -> CTAs 4w..4w+3)
__device__ __forceinline__ void warp_wait(const unsigned* flag, int prod0, unsigned target) {
    int lane = threadIdx.x & 31;
    if (lane < 4) {
        const unsigned* fp = &flag[(prod0 + lane) * 32];
        while (acq_load(fp) < target) { }
    }
    __syncwarp();
}

// ---------------- persistent bidirectional GRU with fused x-projection ----------------
// 128 CTAs x 512 threads: dir = cta>>6, c64 = cta&63. CTA owns cols [c64*8, c64*8+8).
// Full [x,h] k=768 reduction per GEMM: warp w covers h k [32w,32w+32) + x k [16w,16w+16).
// Per-warp producer flags; h and rh parity double-buffered; u stays in registers.
__global__ __launch_bounds__(512, 1) void k_recur(
    const float* __restrict__ fwWg, const float* __restrict__ fwbg,
    const float* __restrict__ fwWc, const float* __restrict__ fwbc,
    const float* __restrict__ bwWg, const float* __restrict__ bwbg,
    const float* __restrict__ bwWc, const float* __restrict__ bwbc)
{
    extern __shared__ float sm[];
    float* Wr_s = sm;              // 8 x 516 (h-part rows 256..767)
    float* Wu_s = sm + 4128;
    float* Wc_s = sm + 8256;
    float* Wrx  = sm + 12384;      // 8 x 260 (x-part rows 0..255)
    float* Wux  = sm + 14464;
    float* Wcx  = sm + 16544;
    float* bR   = sm + 18624;      // 8
    float* bU   = sm + 18632;
    float* bC   = sm + 18640;
    float* redR = sm + 18656;      // 16 warps x 8 cols x 33
    float* redU = sm + 22880;
    float* redC = sm + 27104;

    const int tid = threadIdx.x;
    const int cta = blockIdx.x;
    const int dir = cta >> 6;
    const int c64 = cta & 63;
    const int j0 = c64 * 8;
    const float* Wg = dir ? bwWg : fwWg;
    const float* Wc = dir ? bwWc : fwWc;
    const float* bg = dir ? bwbg : fwbg;
    const float* bc = dir ? bwbc : fwbc;

    for (int idx = tid; idx < 8 * 512; idx += 512) {
        int jj = idx & 7, k = idx >> 3;
        Wr_s[jj * 516 + k] = Wg[(size_t)(256 + k) * 1024 + j0 + jj];
        Wu_s[jj * 516 + k] = Wg[(size_t)(256 + k) * 1024 + 512 + j0 + jj];
        Wc_s[jj * 516 + k] = Wc[(size_t)(256 + k) * 512 + j0 + jj];
    }
    for (int idx = tid; idx < 8 * 256; idx += 512) {
        int jj = idx & 7, k = idx >> 3;
        Wrx[jj * 260 + k] = Wg[(size_t)k * 1024 + j0 + jj];
        Wux[jj * 260 + k] = Wg[(size_t)k * 1024 + 512 + j0 + jj];
        Wcx[jj * 260 + k] = Wc[(size_t)k * 512 + j0 + jj];
    }
    if (tid < 8) {
        bR[tid] = bg[j0 + tid];
        bU[tid] = bg[512 + j0 + tid];
        bC[tid] = bc[j0 + tid];
    }
    __syncthreads();

    const int warp = tid >> 5;
    const int b = tid & 31;
    const int k0 = warp * 32;        // h k-slice
    const int kq0 = warp * 8;        // h k-quad base
    const int kx0 = warp * 16;       // x k-slice
    const int kqx = warp * 4;        // x k-quad base
    const int prod0 = warp * 4;      // this warp's 4 producer CTAs
    const int col = (tid >> 5) & 7;  // epilogue/reduce mapping (tid<256)
    const int eb = tid & 31;
    const int jcol = j0 + col;
    const int hoff = (jcol >> 2) * 128 + eb * 4 + (jcol & 3);

    float* hQbase = g_hQ + (size_t)dir * 2 * 16384;   // + par*16384
    float* rQbase = g_rQ + (size_t)dir * 2 * 16384;
    float* outp = dir ? g_outb : g_outf;
    unsigned* fA = g_flagA[dir];
    unsigned* fB = g_flagB[dir];

    for (int s = 0; s < 512; ++s) {
        const int t = dir ? (511 - s) : s;
        const int wpar = s & 1;          // write parity (state s)
        const int rpar = wpar ^ 1;       // read parity (state s-1)
        float* hRd = hQbase + rpar * 16384;
        float* hWr = hQbase + wpar * 16384;
        float* rBuf = rQbase + wpar * 16384;
        const float* xq = g_xQ + (size_t)t * 8192;

        // ---- x slice loads (independent of flags; latency hides behind wait) ----
        ull xx[8];
#pragma unroll
        for (int q = 0; q < 4; ++q)
            ldcg_v2u64(&xq[(kqx + q) * 128 + b * 4], xx[2 * q], xx[2 * q + 1]);

        // ---- per-warp wait for this warp's h producers (step s-1 done) ----
        warp_wait(fB, prod0, (unsigned)s);

        // ---- load h slice (LDG.128, operands pre-packed) + hold ----
        ull hh[16];
#pragma unroll
        for (int q = 0; q < 8; ++q)
            ldcg_v2u64(&hRd[(kq0 + q) * 128 + b * 4], hh[2 * q], hh[2 * q + 1]);
        float hold = (tid < 256) ? __ldcg(&hRd[hoff]) : 0.f;

        // ---- r GEMM ([x,h] k-768) ----
        {
            ull acc[8];
#pragma unroll
            for (int jj = 0; jj < 8; ++jj) acc[jj] = 0ull;
#pragma unroll
            for (int q2 = 0; q2 < 8; ++q2) {
#pragma unroll
                for (int jj = 0; jj < 8; ++jj) {
                    ulonglong2 ww = *(const ulonglong2*)&Wr_s[jj * 516 + k0 + q2 * 4];
                    FMA2(acc[jj], hh[2 * q2],     ww.x);
                    FMA2(acc[jj], hh[2 * q2 + 1], ww.y);
                }
            }
#pragma unroll
            for (int q2 = 0; q2 < 4; ++q2) {
#pragma unroll
                for (int jj = 0; jj < 8; ++jj) {
                    ulonglong2 ww = *(const ulonglong2*)&Wrx[jj * 260 + kx0 + q2 * 4];
                    FMA2(acc[jj], xx[2 * q2],     ww.x);
                    FMA2(acc[jj], xx[2 * q2 + 1], ww.y);
                }
            }
#pragma unroll
            for (int jj = 0; jj < 8; ++jj) {
                float2 v = unpk(acc[jj]);
                redR[warp * 264 + jj * 33 + b] = v.x + v.y;
            }
        }
        __syncthreads();
        if (tid < 256) {
            float v = bR[col];
#pragma unroll
            for (int q = 0; q < 16; ++q) v += redR[q * 264 + col * 33 + eb];
            float rv = 1.f / (1.f + __expf(-v));
            __stcg(&rBuf[hoff], rv * hold);   // publish rh directly
        }
        arrive_flag(fA, c64, (unsigned)(s + 1));   // rh published (syncthreads inside)

        // ---- u GEMM (hides exchange A); u stays in registers ----
        float ureg = 0.f;
        {
            ull acc[8];
#pragma unroll
            for (int jj = 0; jj < 8; ++jj) acc[jj] = 0ull;
#pragma unroll
            for (int q2 = 0; q2 < 8; ++q2) {
#pragma unroll
                for (int jj = 0; jj < 8; ++jj) {
                    ulonglong2 ww = *(const ulonglong2*)&Wu_s[jj * 516 + k0 + q2 * 4];
                    FMA2(acc[jj], hh[2 * q2],     ww.x);
                    FMA2(acc[jj], hh[2 * q2 + 1], ww.y);
                }
            }
#pragma unroll
            for (int q2 = 0; q2 < 4; ++q2) {
#pragma unroll
                for (int jj = 0; jj < 8; ++jj) {
                    ulonglong2 ww = *(const ulonglong2*)&Wux[jj * 260 + kx0 + q2 * 4];
                    FMA2(acc[jj], xx[2 * q2],     ww.x);
                    FMA2(acc[jj], xx[2 * q2 + 1], ww.y);
                }
            }
#pragma unroll
            for (int jj = 0; jj < 8; ++jj) {
                float2 v = unpk(acc[jj]);
                redU[warp * 264 + jj * 33 + b] = v.x + v.y;
            }
        }
        __syncthreads();
        if (tid < 256) {
            float v = bU[col];
#pragma unroll
            for (int q = 0; q < 16; ++q) v += redU[q * 264 + col * 33 + eb];
            ureg = 1.f / (1.f + __expf(-v));
        }

        // ---- per-warp wait for this warp's rh producers, then candidate ----
        warp_wait(fA, prod0, (unsigned)(s + 1));
        {
#pragma unroll
            for (int q = 0; q < 8; ++q)
                ldcg_v2u64(&rBuf[(kq0 + q) * 128 + b * 4], hh[2 * q], hh[2 * q + 1]);
            ull acc[8];
#pragma unroll
            for (int jj = 0; jj < 8; ++jj) acc[jj] = 0ull;
#pragma unroll
            for (int q2 = 0; q2 < 8; ++q2) {
#pragma unroll
                for (int jj = 0; jj < 8; ++jj) {
                    ulonglong2 ww = *(const ulonglong2*)&Wc_s[jj * 516 + k0 + q2 * 4];
                    FMA2(acc[jj], hh[2 * q2],     ww.x);
                    FMA2(acc[jj], hh[2 * q2 + 1], ww.y);
                }
            }
#pragma unroll
            for (int q2 = 0; q2 < 4; ++q2) {
#pragma unroll
                for (int jj = 0; jj < 8; ++jj) {
                    ulonglong2 ww = *(const ulonglong2*)&Wcx[jj * 260 + kx0 + q2 * 4];
                    FMA2(acc[jj], xx[2 * q2],     ww.x);
                    FMA2(acc[jj], xx[2 * q2 + 1], ww.y);
                }
            }
#pragma unroll
            for (int jj = 0; jj < 8; ++jj) {
                float2 v = unpk(acc[jj]);
                redC[warp * 264 + jj * 33 + b] = v.x + v.y;
            }
        }
        __syncthreads();
        // ---- epilogue: tanh + h update (writes parity buffer of step s) ----
        if (tid < 256) {
            float v = bC[col];
#pragma unroll
            for (int q = 0; q < 16; ++q) v += redC[q * 264 + col * 33 + eb];
            float ct = tanhf(v);
            float hn = ureg * hold + (1.f - ureg) * ct;
            __stcg(&hWr[hoff], hn);
            outp[(size_t)(t * 32 + eb) * 512 + jcol] = hn;
        }
        arrive_flag(fB, c64, (unsigned)(s + 1));
    }
}

// ---------------- FC over shifted-context concat + relu + max-pool, double-buffered ----------------
__global__ __launch_bounds__(256, 2) void k_fc(const float* __restrict__ fcw,
                                               const float* __restrict__ fcb)
{
    __shared__ __align__(16) float As[2][16 * 132];
    __shared__ __align__(16) float Bs[2][16 * 132];
    const int n0 = blockIdx.x * 128;
    const int m0 = blockIdx.y * 128;
    const int tid = threadIdx.x;
    const int tx = tid & 15, ty = tid >> 4;
    const int ar0 = tid >> 2, ac0 = (tid & 3) * 4;
    const int ar1 = (tid + 256) >> 2;
    const int bk0 = tid >> 5, bn0 = (tid & 31) * 4;
    const int bk1 = (tid + 256) >> 5;

    ull acc[8][4];
#pragma unroll
    for (int i = 0; i < 8; i++)
#pragma unroll
        for (int j = 0; j < 4; j++) acc[i][j] = 0ull;

    auto gather = [&](int m, int c) -> float4 {
        float4 v = make_float4(0.f, 0.f, 0.f, 0.f);
        if (c < 512) {
            if (m >= 32) v = *(const float4*)&g_outf[(size_t)(m - 32) * 512 + c];
        } else if (c < 768) {
            v = *(const float4*)&g_xt[(size_t)m * 256 + (c - 512)];
        } else {
            if (m < 16352) v = *(const float4*)&g_outb[(size_t)(m + 32) * 512 + (c - 768)];
        }
        return v;
    };

    float4 pa0, pa1, pb0, pb1;
    pa0 = gather(m0 + ar0, ac0);
    pa1 = gather(m0 + ar1, ac0);
    pb0 = *(const float4*)&fcw[(size_t)bk0 * 512 + n0 + bn0];
    pb1 = *(const float4*)&fcw[(size_t)bk1 * 512 + n0 + bn0];
    {
        As[0][(ac0 + 0) * 132 + ar0] = pa0.x; As[0][(ac0 + 1) * 132 + ar0] = pa0.y;
        As[0][(ac0 + 2) * 132 + ar0] = pa0.z; As[0][(ac0 + 3) * 132 + ar0] = pa0.w;
        As[0][(ac0 + 0) * 132 + ar1] = pa1.x; As[0][(ac0 + 1) * 132 + ar1] = pa1.y;
        As[0][(ac0 + 2) * 132 + ar1] = pa1.z; As[0][(ac0 + 3) * 132 + ar1] = pa1.w;
        *(float4*)&Bs[0][bk0 * 132 + bn0] = pb0;
        *(float4*)&Bs[0][bk1 * 132 + bn0] = pb1;
    }
    __syncthreads();
    int p = 0;
    for (int slab = 0; slab < 80; ++slab) {
        if (slab < 79) {
            int k0 = (slab + 1) * 16;
            pa0 = gather(m0 + ar0, k0 + ac0);
            pa1 = gather(m0 + ar1, k0 + ac0);
            pb0 = *(const float4*)&fcw[(size_t)(k0 + bk0) * 512 + n0 + bn0];
            pb1 = *(const float4*)&fcw[(size_t)(k0 + bk1) * 512 + n0 + bn0];
        }
#pragma unroll
        for (int kk = 0; kk < 16; ++kk) {
            float4 a0 = *(const float4*)&As[p][kk * 132 + ty * 8];
            float4 a1 = *(const float4*)&As[p][kk * 132 + ty * 8 + 4];
            ulonglong2 w01 = *(const ulonglong2*)&Bs[p][kk * 132 + tx * 8];
            ulonglong2 w23 = *(const ulonglong2*)&Bs[p][kk * 132 + tx * 8 + 4];
            ull ad[8];
            ad[0] = dup2f(a0.x); ad[1] = dup2f(a0.y); ad[2] = dup2f(a0.z); ad[3] = dup2f(a0.w);
            ad[4] = dup2f(a1.x); ad[5] = dup2f(a1.y); ad[6] = dup2f(a1.z); ad[7] = dup2f(a1.w);
#pragma unroll
            for (int i = 0; i < 8; i++) {
                FMA2(acc[i][0], ad[i], w01.x);
                FMA2(acc[i][1], ad[i], w01.y);
                FMA2(acc[i][2], ad[i], w23.x);
                FMA2(acc[i][3], ad[i], w23.y);
            }
        }
        if (slab < 79) {
            int q = p ^ 1;
            As[q][(ac0 + 0) * 132 + ar0] = pa0.x; As[q][(ac0 + 1) * 132 + ar0] = pa0.y;
            As[q][(ac0 + 2) * 132 + ar0] = pa0.z; As[q][(ac0 + 3) * 132 + ar0] = pa0.w;
            As[q][(ac0 + 0) * 132 + ar1] = pa1.x; As[q][(ac0 + 1) * 132 + ar1] = pa1.y;
            As[q][(ac0 + 2) * 132 + ar1] = pa1.z; As[q][(ac0 + 3) * 132 + ar1] = pa1.w;
            *(float4*)&Bs[q][bk0 * 132 + bn0] = pb0;
            *(float4*)&Bs[q][bk1 * 132 + bn0] = pb1;
            __syncthreads();
            p = q;
        }
    }
    float4 bb0 = *(const float4*)&fcb[n0 + tx * 8];
    float4 bb1 = *(const float4*)&fcb[n0 + tx * 8 + 4];
    float bcol[8] = {bb0.x, bb0.y, bb0.z, bb0.w, bb1.x, bb1.y, bb1.z, bb1.w};
#pragma unroll
    for (int i = 0; i < 8; i++) {
        int m = m0 + ty * 8 + i;
        int bb = m & 31;
        int base = bb * 512 + n0 + tx * 8;
#pragma unroll
        for (int j = 0; j < 4; j++) {
            float2 v = unpk(acc[i][j]);
            float r0 = fmaxf(v.x + bcol[2 * j], 0.f);
            float r1 = fmaxf(v.y + bcol[2 * j + 1], 0.f);
            atomicMax((int*)&g_pool[base + 2 * j + 0], __float_as_int(r0));
            atomicMax((int*)&g_pool[base + 2 * j + 1], __float_as_int(r1));
        }
    }
}

// ---------------- MLP head ----------------
__global__ void k_mlp(const float* __restrict__ mw, const float* __restrict__ mb,
                      float* __restrict__ out)
{
    __shared__ float sp[512];
    int bb = blockIdx.x;
    int tid = threadIdx.x;
    for (int i = tid; i < 512; i += 256) sp[i] = g_pool[bb * 512 + i];
    __syncthreads();
    float acc = mb[tid];
#pragma unroll 8
    for (int h = 0; h < 512; ++h) acc += sp[h] * mw[h * 256 + tid];
    out[bb * 256 + tid] = acc;
}

// ---------------- launch ----------------
extern "C" void kernel_launch(void* const* d_in, const int* in_sizes, int n_in,
                              void* d_out, int out_size)
{
    const float* x    = (const float*)d_in[0];
    const float* fwWg = (const float*)d_in[1];
    const float* fwbg = (const float*)d_in[2];
    const float* fwWc = (const float*)d_in[3];
    const float* fwbc = (const float*)d_in[4];
    const float* bwWg = (const float*)d_in[5];
    const float* bwbg = (const float*)d_in[6];
    const float* bwWc = (const float*)d_in[7];
    const float* bwbc = (const float*)d_in[8];
    const float* fcw  = (const float*)d_in[9];
    const float* fcb  = (const float*)d_in[10];
    const float* mw   = (const float*)d_in[11];
    const float* mb   = (const float*)d_in[12];
    float* out = (float*)d_out;

    cudaFuncSetAttribute(k_recur, cudaFuncAttributeMaxDynamicSharedMemorySize, 125312);

    k_init<<<256, 256>>>();
    k_xcopy<<<4096, 256>>>(x);
    k_recur<<<128, 512, 125312>>>(fwWg, fwbg, fwWc, fwbc, bwWg, bwbg, bwWc, bwbc);
    k_fc<<<dim3(4, 128), 256>>>(fcw, fcb);
    k_mlp<<<32, 256>>>(mw, mb, out);
}